// round 1
// baseline (speedup 1.0000x reference)
#include <cuda_runtime.h>
#include <cstdint>

#define HIDN   2048
#define NH     16
#define NKV    4
#define HD     128
#define INTERN 8192
#define BATCH  4
#define SEQ    1024
#define TTOK   (BATCH*SEQ)   /* 4096 */
#define EPSV   1e-6f
#define QK_SCALE 0.08838834764831845f  /* 1/sqrt(128) */

// ---------------- scratch (static device allocations, allowed) ----------------
__device__ float g_h   [TTOK * HIDN];
__device__ float g_q   [TTOK * NH  * HD];
__device__ float g_k   [TTOK * NKV * HD];
__device__ float g_v   [TTOK * NKV * HD];
__device__ float g_attn[TTOK * HIDN];
__device__ float g_x1  [TTOK * HIDN];
__device__ float g_gate[TTOK * INTERN];
__device__ float g_up  [TTOK * INTERN];

// ---------------- tf32 mma helpers ----------------
__device__ __forceinline__ uint32_t f2tf(float f) {
    uint32_t u; asm("cvt.rna.tf32.f32 %0, %1;" : "=r"(u) : "f"(f)); return u;
}
__device__ __forceinline__ void mma_tf32(float c[4], const uint32_t a[4], const uint32_t b[2]) {
    asm volatile("mma.sync.aligned.m16n8k8.row.col.f32.tf32.tf32.f32 "
        "{%0,%1,%2,%3}, {%4,%5,%6,%7}, {%8,%9}, {%0,%1,%2,%3};\n"
        : "+f"(c[0]), "+f"(c[1]), "+f"(c[2]), "+f"(c[3])
        : "r"(a[0]), "r"(a[1]), "r"(a[2]), "r"(a[3]), "r"(b[0]), "r"(b[1]));
}

// ---------------- GEMM: C[M,N] = A[M,K] @ B[N,K]^T (+bias[n]) (+res[m,n]) ----------------
// tiles: BM=128, BN=128, BK=16; 256 threads = 8 warps (2 M x 4 N), warp tile 64x32.
__global__ __launch_bounds__(256)
void gemm_tf32(const float* __restrict__ A, const float* __restrict__ B,
               const float* __restrict__ bias, const float* __restrict__ res,
               float* __restrict__ C, int M, int N, int K) {
    __shared__ float As[2][2560];   // 128 rows * stride 20
    __shared__ float Bs[2][2560];

    const int tid  = threadIdx.x;
    const int lane = tid & 31, warp = tid >> 5;
    const int wm = warp & 1, wn = warp >> 1;
    const int g  = lane >> 2, t4 = lane & 3;
    const int brow = blockIdx.y << 7, bcol = blockIdx.x << 7;

    // global->smem loader mapping: 512 float4 slots, 256 threads x 2
    const int lr = tid >> 2;               // 0..63
    const int lc = (tid & 3) << 2;         // 0,4,8,12
    const float* aptr = A + (size_t)(brow + lr) * K + lc;
    const float* bptr = B + (size_t)(bcol + lr) * K + lc;
    const int soff = lr * 20 + lc;

    float acc[4][4][4];
#pragma unroll
    for (int i = 0; i < 4; i++)
#pragma unroll
        for (int j = 0; j < 4; j++)
#pragma unroll
            for (int e = 0; e < 4; e++) acc[i][j][e] = 0.f;

    // preload tile 0
    {
        float4 a0 = *(const float4*)aptr;
        float4 a1 = *(const float4*)(aptr + (size_t)64 * K);
        float4 b0 = *(const float4*)bptr;
        float4 b1 = *(const float4*)(bptr + (size_t)64 * K);
        *(float4*)&As[0][soff]        = a0;
        *(float4*)&As[0][soff + 1280] = a1;
        *(float4*)&Bs[0][soff]        = b0;
        *(float4*)&Bs[0][soff + 1280] = b1;
    }
    __syncthreads();

    const int nk = K >> 4;
    float4 ra0, ra1, rb0, rb1;
    for (int t = 0; t < nk; ++t) {
        const int cur = t & 1;
        if (t + 1 < nk) {
            const float* ap = aptr + (size_t)(t + 1) * 16;
            const float* bp = bptr + (size_t)(t + 1) * 16;
            ra0 = *(const float4*)ap;
            ra1 = *(const float4*)(ap + (size_t)64 * K);
            rb0 = *(const float4*)bp;
            rb1 = *(const float4*)(bp + (size_t)64 * K);
        }
        const float* As_ = As[cur];
        const float* Bs_ = Bs[cur];
#pragma unroll
        for (int kb = 0; kb < 16; kb += 8) {
            uint32_t af[4][4], bf[4][2];
#pragma unroll
            for (int mt = 0; mt < 4; ++mt) {
                int base = (wm * 64 + mt * 16 + g) * 20 + kb + t4;
                af[mt][0] = f2tf(As_[base]);
                af[mt][1] = f2tf(As_[base + 160]);
                af[mt][2] = f2tf(As_[base + 4]);
                af[mt][3] = f2tf(As_[base + 164]);
            }
#pragma unroll
            for (int nt = 0; nt < 4; ++nt) {
                int nbase = (wn * 32 + nt * 8 + g) * 20 + kb + t4;
                bf[nt][0] = f2tf(Bs_[nbase]);
                bf[nt][1] = f2tf(Bs_[nbase + 4]);
            }
#pragma unroll
            for (int mt = 0; mt < 4; ++mt)
#pragma unroll
                for (int nt = 0; nt < 4; ++nt)
                    mma_tf32(acc[mt][nt], af[mt], bf[nt]);
        }
        __syncthreads();
        if (t + 1 < nk) {
            const int nxt = cur ^ 1;
            *(float4*)&As[nxt][soff]        = ra0;
            *(float4*)&As[nxt][soff + 1280] = ra1;
            *(float4*)&Bs[nxt][soff]        = rb0;
            *(float4*)&Bs[nxt][soff + 1280] = rb1;
            __syncthreads();
        }
    }

    // epilogue
#pragma unroll
    for (int mt = 0; mt < 4; ++mt) {
        int r0 = brow + wm * 64 + mt * 16 + g;
#pragma unroll
        for (int nt = 0; nt < 4; ++nt) {
            int c0 = bcol + wn * 32 + nt * 8 + t4 * 2;
            float2 v0 = make_float2(acc[mt][nt][0], acc[mt][nt][1]);
            float2 v1 = make_float2(acc[mt][nt][2], acc[mt][nt][3]);
            if (bias) {
                float2 bv = *(const float2*)&bias[c0];
                v0.x += bv.x; v0.y += bv.y; v1.x += bv.x; v1.y += bv.y;
            }
            if (res) {
                float2 ra = *(const float2*)&res[(size_t)r0 * N + c0];
                float2 rb = *(const float2*)&res[(size_t)(r0 + 8) * N + c0];
                v0.x += ra.x; v0.y += ra.y; v1.x += rb.x; v1.y += rb.y;
            }
            *(float2*)&C[(size_t)r0 * N + c0]       = v0;
            *(float2*)&C[(size_t)(r0 + 8) * N + c0] = v1;
        }
    }
}

// ---------------- RMSNorm over HIDN=2048 (one block per row) ----------------
__global__ void rmsnorm_kernel(const float* __restrict__ x, const float* __restrict__ w,
                               float* __restrict__ out) {
    int row = blockIdx.x;
    const float* xr = x + (size_t)row * HIDN;
    float4 v[2];
    float ss = 0.f;
#pragma unroll
    for (int i = 0; i < 2; i++) {
        v[i] = *(const float4*)&xr[(threadIdx.x + i * 256) * 4];
        ss += v[i].x * v[i].x + v[i].y * v[i].y + v[i].z * v[i].z + v[i].w * v[i].w;
    }
#pragma unroll
    for (int o = 16; o; o >>= 1) ss += __shfl_xor_sync(~0u, ss, o);
    __shared__ float red[8];
    if ((threadIdx.x & 31) == 0) red[threadIdx.x >> 5] = ss;
    __syncthreads();
    if (threadIdx.x == 0) {
        float t = 0.f;
#pragma unroll
        for (int i = 0; i < 8; i++) t += red[i];
        red[0] = rsqrtf(t / (float)HIDN + EPSV);
    }
    __syncthreads();
    float r = red[0];
#pragma unroll
    for (int i = 0; i < 2; i++) {
        int c = (threadIdx.x + i * 256) * 4;
        float4 wv = *(const float4*)&w[c];
        float4 o4 = make_float4(v[i].x * r * wv.x, v[i].y * r * wv.y,
                                v[i].z * r * wv.z, v[i].w * r * wv.w);
        *(float4*)&out[(size_t)row * HIDN + c] = o4;
    }
}

// ---------------- per-head RMSNorm + RoPE (in place on q / k) ----------------
__global__ void qknorm_rope_kernel(float* __restrict__ qb, float* __restrict__ kb,
                                   const float* __restrict__ qw, const float* __restrict__ kw,
                                   const float* __restrict__ cs, const float* __restrict__ sn) {
    int token = blockIdx.x, h = blockIdx.y;
    float* p; const float* w;
    if (h < NH) { p = qb + (size_t)token * (NH * HD)  + h * HD;        w = qw; }
    else        { p = kb + (size_t)token * (NKV * HD) + (h - NH) * HD; w = kw; }
    int d = threadIdx.x;
    float v = p[d];
    float ss = v * v;
#pragma unroll
    for (int o = 16; o; o >>= 1) ss += __shfl_xor_sync(~0u, ss, o);
    __shared__ float red[4];
    __shared__ float sh[128];
    if ((d & 31) == 0) red[d >> 5] = ss;
    __syncthreads();
    float tot = red[0] + red[1] + red[2] + red[3];
    float r = rsqrtf(tot / 128.f + EPSV);
    float xn = v * r * w[d];
    sh[d] = xn;
    __syncthreads();
    float rot = (d < 64) ? -sh[d + 64] : sh[d - 64];
    float c = cs[(size_t)token * 128 + d], s = sn[(size_t)token * 128 + d];
    p[d] = xn * c + rot * s;
}

// ---------------- flash attention (fp32, causal, GQA) ----------------
// grid (S/64, H, B), 256 threads. q-tile 64, k-tile 64.
// thread (tr=tid/16, tc=tid%16): S rows {tr+16i}, S cols {tc+16j};
// O rows {tr+16i}, O cols {4tc..4tc+3, 64+4tc..64+4tc+3}.
#define ATTN_SMEM_FLOATS (3 * 64 * 132 + 3 * 64)
__global__ __launch_bounds__(256)
void attn_kernel(const float* __restrict__ q, const float* __restrict__ k,
                 const float* __restrict__ v, float* __restrict__ o) {
    extern __shared__ float sm[];
    float* Qs   = sm;                 // 64 x 132
    float* KP   = sm + 64 * 132;      // K tile (stride 132) / P tile (stride 68) union
    float* Vs   = sm + 2 * 64 * 132;  // 64 x 132
    float* Mrow = sm + 3 * 64 * 132;
    float* Lrow = Mrow + 64;
    float* Arow = Lrow + 64;

    const int tid = threadIdx.x;
    const int tr = tid >> 4, tc = tid & 15;
    const int qt = blockIdx.x, hq = blockIdx.y, b = blockIdx.z;
    const int kvh = hq >> 2;
    const int tok0 = b * SEQ + qt * 64;
    const int cA = 4 * tc, cB = 64 + 4 * tc;

    // load Q tile (scaled)
    for (int l = tid; l < 2048; l += 256) {
        int r = l >> 5, d4 = (l & 31) * 4;
        float4 qv = *(const float4*)&q[(size_t)(tok0 + r) * (NH * HD) + hq * HD + d4];
        qv.x *= QK_SCALE; qv.y *= QK_SCALE; qv.z *= QK_SCALE; qv.w *= QK_SCALE;
        *(float4*)&Qs[r * 132 + d4] = qv;
    }
    if (tid < 64) { Mrow[tid] = -3.0e38f; Lrow[tid] = 0.f; }
    float O[4][8];
#pragma unroll
    for (int i = 0; i < 4; i++)
#pragma unroll
        for (int m = 0; m < 8; m++) O[i][m] = 0.f;
    __syncthreads();

    for (int kt = 0; kt <= qt; ++kt) {
        // load K,V tiles
        for (int l = tid; l < 2048; l += 256) {
            int r = l >> 5, d4 = (l & 31) * 4;
            size_t base = (size_t)(b * SEQ + kt * 64 + r) * (NKV * HD) + kvh * HD + d4;
            *(float4*)&KP[r * 132 + d4] = *(const float4*)&k[base];
            *(float4*)&Vs[r * 132 + d4] = *(const float4*)&v[base];
        }
        __syncthreads();

        // S = Q K^T
        float s[4][4];
#pragma unroll
        for (int i = 0; i < 4; i++)
#pragma unroll
            for (int j = 0; j < 4; j++) s[i][j] = 0.f;
        for (int kk = 0; kk < 128; kk += 4) {
            float4 q4[4], k4[4];
#pragma unroll
            for (int i = 0; i < 4; i++) q4[i] = *(const float4*)&Qs[(tr + 16 * i) * 132 + kk];
#pragma unroll
            for (int j = 0; j < 4; j++) k4[j] = *(const float4*)&KP[(tc + 16 * j) * 132 + kk];
#pragma unroll
            for (int i = 0; i < 4; i++)
#pragma unroll
                for (int j = 0; j < 4; j++)
                    s[i][j] += q4[i].x * k4[j].x + q4[i].y * k4[j].y
                             + q4[i].z * k4[j].z + q4[i].w * k4[j].w;
        }
        __syncthreads();  // done reading K tile; KP becomes P tile

        const bool diag = (kt == qt);
#pragma unroll
        for (int i = 0; i < 4; i++) {
            int rl = tr + 16 * i;
            if (diag) {
#pragma unroll
                for (int j = 0; j < 4; j++)
                    if (tc + 16 * j > rl) s[i][j] = -1.0e30f;
            }
            float mx = fmaxf(fmaxf(s[i][0], s[i][1]), fmaxf(s[i][2], s[i][3]));
#pragma unroll
            for (int off = 1; off < 16; off <<= 1) mx = fmaxf(mx, __shfl_xor_sync(~0u, mx, off));
            float mold = Mrow[rl];
            float mnew = fmaxf(mold, mx);
            float psum = 0.f;
#pragma unroll
            for (int j = 0; j < 4; j++) {
                float p = __expf(s[i][j] - mnew);
                KP[rl * 68 + tc + 16 * j] = p;   // P tile, stride 68
                psum += p;
            }
#pragma unroll
            for (int off = 1; off < 16; off <<= 1) psum += __shfl_xor_sync(~0u, psum, off);
            if (tc == 0) {
                float al = __expf(mold - mnew);
                Mrow[rl] = mnew;
                Lrow[rl] = Lrow[rl] * al + psum;
                Arow[rl] = al;
            }
        }
        __syncthreads();

        // rescale O, then O += P V
#pragma unroll
        for (int i = 0; i < 4; i++) {
            float al = Arow[tr + 16 * i];
#pragma unroll
            for (int m = 0; m < 8; m++) O[i][m] *= al;
        }
#pragma unroll 4
        for (int j = 0; j < 64; j++) {
            float4 vA = *(const float4*)&Vs[j * 132 + cA];
            float4 vB = *(const float4*)&Vs[j * 132 + cB];
#pragma unroll
            for (int i = 0; i < 4; i++) {
                float p = KP[(tr + 16 * i) * 68 + j];
                O[i][0] += p * vA.x; O[i][1] += p * vA.y;
                O[i][2] += p * vA.z; O[i][3] += p * vA.w;
                O[i][4] += p * vB.x; O[i][5] += p * vB.y;
                O[i][6] += p * vB.z; O[i][7] += p * vB.w;
            }
        }
        __syncthreads();  // before next tile overwrites KP / Vs
    }

    // epilogue: divide by row sum, write out
#pragma unroll
    for (int i = 0; i < 4; i++) {
        int rl = tr + 16 * i;
        float inv = 1.f / Lrow[rl];
        float4 oA = make_float4(O[i][0] * inv, O[i][1] * inv, O[i][2] * inv, O[i][3] * inv);
        float4 oB = make_float4(O[i][4] * inv, O[i][5] * inv, O[i][6] * inv, O[i][7] * inv);
        size_t base = (size_t)(tok0 + rl) * (NH * HD) + hq * HD;
        *(float4*)&o[base + cA] = oA;
        *(float4*)&o[base + cB] = oB;
    }
}

// ---------------- SiLU(gate) * up, in place on gate ----------------
__global__ void silu_mul_kernel(float* __restrict__ gbuf, const float* __restrict__ ubuf, int n4) {
    int i = blockIdx.x * blockDim.x + threadIdx.x;
    if (i < n4) {
        float4 gv = ((const float4*)gbuf)[i];
        float4 uv = ((const float4*)ubuf)[i];
        gv.x = gv.x / (1.f + __expf(-gv.x)) * uv.x;
        gv.y = gv.y / (1.f + __expf(-gv.y)) * uv.y;
        gv.z = gv.z / (1.f + __expf(-gv.z)) * uv.z;
        gv.w = gv.w / (1.f + __expf(-gv.w)) * uv.w;
        ((float4*)gbuf)[i] = gv;
    }
}

// ---------------- host orchestration ----------------
extern "C" void kernel_launch(void* const* d_in, const int* in_sizes, int n_in,
                              void* d_out, int out_size) {
    const float* x    = (const float*)d_in[0];
    // d_in[1] = attention_mask (causal, implicit) — unused
    const float* cosb = (const float*)d_in[2];
    const float* sinb = (const float*)d_in[3];
    const float* wq   = (const float*)d_in[4];
    const float* bq   = (const float*)d_in[5];
    const float* wk   = (const float*)d_in[6];
    const float* bk   = (const float*)d_in[7];
    const float* wv   = (const float*)d_in[8];
    const float* bv   = (const float*)d_in[9];
    const float* wo   = (const float*)d_in[10];
    const float* qnw  = (const float*)d_in[11];
    const float* knw  = (const float*)d_in[12];
    const float* ln1  = (const float*)d_in[13];
    const float* ln2  = (const float*)d_in[14];
    const float* wg   = (const float*)d_in[15];
    const float* wu   = (const float*)d_in[16];
    const float* wd   = (const float*)d_in[17];
    float* out = (float*)d_out;

    float *h_, *q_, *k_, *v_, *attn_, *x1_, *gate_, *up_;
    cudaGetSymbolAddress((void**)&h_,    g_h);
    cudaGetSymbolAddress((void**)&q_,    g_q);
    cudaGetSymbolAddress((void**)&k_,    g_k);
    cudaGetSymbolAddress((void**)&v_,    g_v);
    cudaGetSymbolAddress((void**)&attn_, g_attn);
    cudaGetSymbolAddress((void**)&x1_,   g_x1);
    cudaGetSymbolAddress((void**)&gate_, g_gate);
    cudaGetSymbolAddress((void**)&up_,   g_up);

    const int attn_smem = ATTN_SMEM_FLOATS * 4;
    cudaFuncSetAttribute(attn_kernel, cudaFuncAttributeMaxDynamicSharedMemorySize, attn_smem);

    // 1. h = RMSNorm(x, ln1)
    rmsnorm_kernel<<<TTOK, 256>>>(x, ln1, h_);
    // 2-4. q/k/v projections (+ zero bias, harmless)
    gemm_tf32<<<dim3(HIDN / 128, TTOK / 128), 256>>>(h_, wq, bq, nullptr, q_, TTOK, HIDN, HIDN);
    gemm_tf32<<<dim3((NKV * HD) / 128, TTOK / 128), 256>>>(h_, wk, bk, nullptr, k_, TTOK, NKV * HD, HIDN);
    gemm_tf32<<<dim3((NKV * HD) / 128, TTOK / 128), 256>>>(h_, wv, bv, nullptr, v_, TTOK, NKV * HD, HIDN);
    // 5. per-head RMSNorm + RoPE on q and k
    qknorm_rope_kernel<<<dim3(TTOK, NH + NKV), 128>>>(q_, k_, qnw, knw, cosb, sinb);
    // 6. causal flash attention
    attn_kernel<<<dim3(SEQ / 64, NH, BATCH), 256, attn_smem>>>(q_, k_, v_, attn_);
    // 7. x1 = x + attn @ wo^T
    gemm_tf32<<<dim3(HIDN / 128, TTOK / 128), 256>>>(attn_, wo, nullptr, x, x1_, TTOK, HIDN, HIDN);
    // 8. h2 = RMSNorm(x1, ln2)
    rmsnorm_kernel<<<TTOK, 256>>>(x1_, ln2, h_);
    // 9-10. gate / up projections
    gemm_tf32<<<dim3(INTERN / 128, TTOK / 128), 256>>>(h_, wg, nullptr, nullptr, gate_, TTOK, INTERN, HIDN);
    gemm_tf32<<<dim3(INTERN / 128, TTOK / 128), 256>>>(h_, wu, nullptr, nullptr, up_, TTOK, INTERN, HIDN);
    // 11. gate = silu(gate) * up
    {
        int n4 = TTOK * INTERN / 4;
        silu_mul_kernel<<<(n4 + 255) / 256, 256>>>(gate_, up_, n4);
    }
    // 12. out = x1 + gate @ wd^T
    gemm_tf32<<<dim3(HIDN / 128, TTOK / 128), 256>>>(gate_, wd, nullptr, x1_, out, TTOK, HIDN, INTERN);
}

// round 2
// speedup vs baseline: 1.2720x; 1.2720x over previous
#include <cuda_runtime.h>
#include <cstdint>

#define HIDN   2048
#define NH     16
#define NKV    4
#define HD     128
#define INTERN 8192
#define BATCH  4
#define SEQ    1024
#define TTOK   (BATCH*SEQ)   /* 4096 */
#define EPSV   1e-6f
#define QK_SCALE 0.08838834764831845f  /* 1/sqrt(128) */

// ---------------- scratch (static device allocations, allowed) ----------------
__device__ float g_h   [TTOK * HIDN];
__device__ float g_q   [TTOK * NH  * HD];
__device__ float g_k   [TTOK * NKV * HD];
__device__ float g_v   [TTOK * NKV * HD];
__device__ float g_attn[TTOK * HIDN];
__device__ float g_x1  [TTOK * HIDN];
__device__ float g_gate[TTOK * INTERN];
__device__ float g_up  [TTOK * INTERN];

// ---------------- tf32 mma helpers ----------------
__device__ __forceinline__ uint32_t f2tf(float f) {
    uint32_t u; asm("cvt.rna.tf32.f32 %0, %1;" : "=r"(u) : "f"(f)); return u;
}
__device__ __forceinline__ uint4 f2tf4(float4 v) {
    uint4 u;
    u.x = f2tf(v.x); u.y = f2tf(v.y); u.z = f2tf(v.z); u.w = f2tf(v.w);
    return u;
}
__device__ __forceinline__ void mma_tf32(float c[4], const uint32_t a[4], const uint32_t b[2]) {
    asm volatile("mma.sync.aligned.m16n8k8.row.col.f32.tf32.tf32.f32 "
        "{%0,%1,%2,%3}, {%4,%5,%6,%7}, {%8,%9}, {%0,%1,%2,%3};\n"
        : "+f"(c[0]), "+f"(c[1]), "+f"(c[2]), "+f"(c[3])
        : "r"(a[0]), "r"(a[1]), "r"(a[2]), "r"(a[3]), "r"(b[0]), "r"(b[1]));
}

// ---------------- GEMM: C[M,N] = A[M,K] @ B[N,K]^T (+bias[n]) (+res[m,n]) ----------------
// tiles: BM=128, BN=128, BK=32; 256 threads = 8 warps (2 M x 4 N), warp tile 64x32.
// smem holds PRE-CONVERTED tf32 (u32) words — no cvt in the inner loop.
// stride 36 u32 per row: fragment loads conflict-free ((4g+t4) distinct mod 32).
#define GSTRIDE 36
#define GBUF    (128 * GSTRIDE)   /* 4608 u32 = 18432 B per matrix per stage */
#define GEMM_SMEM_BYTES (4 * GBUF * 4)

__global__ __launch_bounds__(256)
void gemm_tf32(const float* __restrict__ A, const float* __restrict__ B,
               const float* __restrict__ bias, const float* __restrict__ res,
               float* __restrict__ C, int M, int N, int K) {
    extern __shared__ uint32_t smem[];
    uint32_t* As = smem;            // [2][GBUF]
    uint32_t* Bs = smem + 2 * GBUF; // [2][GBUF]

    const int tid  = threadIdx.x;
    const int lane = tid & 31, warp = tid >> 5;
    const int wm = warp & 1, wn = warp >> 1;
    const int g  = lane >> 2, t4 = lane & 3;
    const int brow = blockIdx.y << 7, bcol = blockIdx.x << 7;

    // loader mapping: thread covers 4 rows (lr, +32, +64, +96), 4 cols (lc..lc+3)
    const int lr = tid >> 3;            // 0..31
    const int lc = (tid & 7) << 2;      // 0,4,...,28
    const float* aptr = A + (size_t)(brow + lr) * K + lc;
    const float* bptr = B + (size_t)(bcol + lr) * K + lc;
    const int soff = lr * GSTRIDE + lc;

    float acc[4][4][4];
#pragma unroll
    for (int i = 0; i < 4; i++)
#pragma unroll
        for (int j = 0; j < 4; j++)
#pragma unroll
            for (int e = 0; e < 4; e++) acc[i][j][e] = 0.f;

    float4 ra[4], rb[4];
    // preload tile 0
#pragma unroll
    for (int r = 0; r < 4; r++) {
        ra[r] = *(const float4*)(aptr + (size_t)(r * 32) * K);
        rb[r] = *(const float4*)(bptr + (size_t)(r * 32) * K);
    }
#pragma unroll
    for (int r = 0; r < 4; r++) {
        *(uint4*)&As[soff + r * 32 * GSTRIDE] = f2tf4(ra[r]);
        *(uint4*)&Bs[soff + r * 32 * GSTRIDE] = f2tf4(rb[r]);
    }
    __syncthreads();

    const int nk = K >> 5;
    for (int t = 0; t < nk; ++t) {
        const int cur = t & 1;
        if (t + 1 < nk) {
            const float* ap = aptr + (size_t)(t + 1) * 32;
            const float* bp = bptr + (size_t)(t + 1) * 32;
#pragma unroll
            for (int r = 0; r < 4; r++) {
                ra[r] = *(const float4*)(ap + (size_t)(r * 32) * K);
                rb[r] = *(const float4*)(bp + (size_t)(r * 32) * K);
            }
        }
        const uint32_t* As_ = As + cur * GBUF;
        const uint32_t* Bs_ = Bs + cur * GBUF;
#pragma unroll
        for (int kb = 0; kb < 32; kb += 8) {
            uint32_t af[4][4], bf[4][2];
#pragma unroll
            for (int mt = 0; mt < 4; ++mt) {
                int base = (wm * 64 + mt * 16 + g) * GSTRIDE + kb + t4;
                af[mt][0] = As_[base];
                af[mt][1] = As_[base + 8 * GSTRIDE];
                af[mt][2] = As_[base + 4];
                af[mt][3] = As_[base + 8 * GSTRIDE + 4];
            }
#pragma unroll
            for (int nt = 0; nt < 4; ++nt) {
                int nbase = (wn * 32 + nt * 8 + g) * GSTRIDE + kb + t4;
                bf[nt][0] = Bs_[nbase];
                bf[nt][1] = Bs_[nbase + 4];
            }
#pragma unroll
            for (int mt = 0; mt < 4; ++mt)
#pragma unroll
                for (int nt = 0; nt < 4; ++nt)
                    mma_tf32(acc[mt][nt], af[mt], bf[nt]);
        }
        __syncthreads();
        if (t + 1 < nk) {
            uint32_t* An = As + (cur ^ 1) * GBUF;
            uint32_t* Bn = Bs + (cur ^ 1) * GBUF;
#pragma unroll
            for (int r = 0; r < 4; r++) {
                *(uint4*)&An[soff + r * 32 * GSTRIDE] = f2tf4(ra[r]);
                *(uint4*)&Bn[soff + r * 32 * GSTRIDE] = f2tf4(rb[r]);
            }
            __syncthreads();
        }
    }

    // epilogue
#pragma unroll
    for (int mt = 0; mt < 4; ++mt) {
        int r0 = brow + wm * 64 + mt * 16 + g;
#pragma unroll
        for (int nt = 0; nt < 4; ++nt) {
            int c0 = bcol + wn * 32 + nt * 8 + t4 * 2;
            float2 v0 = make_float2(acc[mt][nt][0], acc[mt][nt][1]);
            float2 v1 = make_float2(acc[mt][nt][2], acc[mt][nt][3]);
            if (bias) {
                float2 bv = *(const float2*)&bias[c0];
                v0.x += bv.x; v0.y += bv.y; v1.x += bv.x; v1.y += bv.y;
            }
            if (res) {
                float2 rra = *(const float2*)&res[(size_t)r0 * N + c0];
                float2 rrb = *(const float2*)&res[(size_t)(r0 + 8) * N + c0];
                v0.x += rra.x; v0.y += rra.y; v1.x += rrb.x; v1.y += rrb.y;
            }
            *(float2*)&C[(size_t)r0 * N + c0]       = v0;
            *(float2*)&C[(size_t)(r0 + 8) * N + c0] = v1;
        }
    }
}

// ---------------- RMSNorm over HIDN=2048 (one block per row) ----------------
__global__ void rmsnorm_kernel(const float* __restrict__ x, const float* __restrict__ w,
                               float* __restrict__ out) {
    int row = blockIdx.x;
    const float* xr = x + (size_t)row * HIDN;
    float4 v[2];
    float ss = 0.f;
#pragma unroll
    for (int i = 0; i < 2; i++) {
        v[i] = *(const float4*)&xr[(threadIdx.x + i * 256) * 4];
        ss += v[i].x * v[i].x + v[i].y * v[i].y + v[i].z * v[i].z + v[i].w * v[i].w;
    }
#pragma unroll
    for (int o = 16; o; o >>= 1) ss += __shfl_xor_sync(~0u, ss, o);
    __shared__ float red[8];
    if ((threadIdx.x & 31) == 0) red[threadIdx.x >> 5] = ss;
    __syncthreads();
    if (threadIdx.x == 0) {
        float t = 0.f;
#pragma unroll
        for (int i = 0; i < 8; i++) t += red[i];
        red[0] = rsqrtf(t / (float)HIDN + EPSV);
    }
    __syncthreads();
    float r = red[0];
#pragma unroll
    for (int i = 0; i < 2; i++) {
        int c = (threadIdx.x + i * 256) * 4;
        float4 wv = *(const float4*)&w[c];
        float4 o4 = make_float4(v[i].x * r * wv.x, v[i].y * r * wv.y,
                                v[i].z * r * wv.z, v[i].w * r * wv.w);
        *(float4*)&out[(size_t)row * HIDN + c] = o4;
    }
}

// ---------------- per-head RMSNorm + RoPE (in place on q / k) ----------------
__global__ void qknorm_rope_kernel(float* __restrict__ qb, float* __restrict__ kb,
                                   const float* __restrict__ qw, const float* __restrict__ kw,
                                   const float* __restrict__ cs, const float* __restrict__ sn) {
    int token = blockIdx.x, h = blockIdx.y;
    float* p; const float* w;
    if (h < NH) { p = qb + (size_t)token * (NH * HD)  + h * HD;        w = qw; }
    else        { p = kb + (size_t)token * (NKV * HD) + (h - NH) * HD; w = kw; }
    int d = threadIdx.x;
    float v = p[d];
    float ss = v * v;
#pragma unroll
    for (int o = 16; o; o >>= 1) ss += __shfl_xor_sync(~0u, ss, o);
    __shared__ float red[4];
    __shared__ float sh[128];
    if ((d & 31) == 0) red[d >> 5] = ss;
    __syncthreads();
    float tot = red[0] + red[1] + red[2] + red[3];
    float r = rsqrtf(tot / 128.f + EPSV);
    float xn = v * r * w[d];
    sh[d] = xn;
    __syncthreads();
    float rot = (d < 64) ? -sh[d + 64] : sh[d - 64];
    float c = cs[(size_t)token * 128 + d], s = sn[(size_t)token * 128 + d];
    p[d] = xn * c + rot * s;
}

// ---------------- flash attention (fp32, causal, GQA) ----------------
#define ATTN_SMEM_FLOATS (3 * 64 * 132 + 3 * 64)
__global__ __launch_bounds__(256)
void attn_kernel(const float* __restrict__ q, const float* __restrict__ k,
                 const float* __restrict__ v, float* __restrict__ o) {
    extern __shared__ float sm[];
    float* Qs   = sm;                 // 64 x 132
    float* KP   = sm + 64 * 132;      // K tile (stride 132) / P tile (stride 68) union
    float* Vs   = sm + 2 * 64 * 132;  // 64 x 132
    float* Mrow = sm + 3 * 64 * 132;
    float* Lrow = Mrow + 64;
    float* Arow = Lrow + 64;

    const int tid = threadIdx.x;
    const int tr = tid >> 4, tc = tid & 15;
    const int qt = blockIdx.x, hq = blockIdx.y, b = blockIdx.z;
    const int kvh = hq >> 2;
    const int tok0 = b * SEQ + qt * 64;
    const int cA = 4 * tc, cB = 64 + 4 * tc;

    for (int l = tid; l < 2048; l += 256) {
        int r = l >> 5, d4 = (l & 31) * 4;
        float4 qv = *(const float4*)&q[(size_t)(tok0 + r) * (NH * HD) + hq * HD + d4];
        qv.x *= QK_SCALE; qv.y *= QK_SCALE; qv.z *= QK_SCALE; qv.w *= QK_SCALE;
        *(float4*)&Qs[r * 132 + d4] = qv;
    }
    if (tid < 64) { Mrow[tid] = -3.0e38f; Lrow[tid] = 0.f; }
    float O[4][8];
#pragma unroll
    for (int i = 0; i < 4; i++)
#pragma unroll
        for (int m = 0; m < 8; m++) O[i][m] = 0.f;
    __syncthreads();

    for (int kt = 0; kt <= qt; ++kt) {
        for (int l = tid; l < 2048; l += 256) {
            int r = l >> 5, d4 = (l & 31) * 4;
            size_t base = (size_t)(b * SEQ + kt * 64 + r) * (NKV * HD) + kvh * HD + d4;
            *(float4*)&KP[r * 132 + d4] = *(const float4*)&k[base];
            *(float4*)&Vs[r * 132 + d4] = *(const float4*)&v[base];
        }
        __syncthreads();

        float s[4][4];
#pragma unroll
        for (int i = 0; i < 4; i++)
#pragma unroll
            for (int j = 0; j < 4; j++) s[i][j] = 0.f;
        for (int kk = 0; kk < 128; kk += 4) {
            float4 q4[4], k4[4];
#pragma unroll
            for (int i = 0; i < 4; i++) q4[i] = *(const float4*)&Qs[(tr + 16 * i) * 132 + kk];
#pragma unroll
            for (int j = 0; j < 4; j++) k4[j] = *(const float4*)&KP[(tc + 16 * j) * 132 + kk];
#pragma unroll
            for (int i = 0; i < 4; i++)
#pragma unroll
                for (int j = 0; j < 4; j++)
                    s[i][j] += q4[i].x * k4[j].x + q4[i].y * k4[j].y
                             + q4[i].z * k4[j].z + q4[i].w * k4[j].w;
        }
        __syncthreads();

        const bool diag = (kt == qt);
#pragma unroll
        for (int i = 0; i < 4; i++) {
            int rl = tr + 16 * i;
            if (diag) {
#pragma unroll
                for (int j = 0; j < 4; j++)
                    if (tc + 16 * j > rl) s[i][j] = -1.0e30f;
            }
            float mx = fmaxf(fmaxf(s[i][0], s[i][1]), fmaxf(s[i][2], s[i][3]));
#pragma unroll
            for (int off = 1; off < 16; off <<= 1) mx = fmaxf(mx, __shfl_xor_sync(~0u, mx, off));
            float mold = Mrow[rl];
            float mnew = fmaxf(mold, mx);
            float psum = 0.f;
#pragma unroll
            for (int j = 0; j < 4; j++) {
                float p = __expf(s[i][j] - mnew);
                KP[rl * 68 + tc + 16 * j] = p;
                psum += p;
            }
#pragma unroll
            for (int off = 1; off < 16; off <<= 1) psum += __shfl_xor_sync(~0u, psum, off);
            if (tc == 0) {
                float al = __expf(mold - mnew);
                Mrow[rl] = mnew;
                Lrow[rl] = Lrow[rl] * al + psum;
                Arow[rl] = al;
            }
        }
        __syncthreads();

#pragma unroll
        for (int i = 0; i < 4; i++) {
            float al = Arow[tr + 16 * i];
#pragma unroll
            for (int m = 0; m < 8; m++) O[i][m] *= al;
        }
#pragma unroll 4
        for (int j = 0; j < 64; j++) {
            float4 vA = *(const float4*)&Vs[j * 132 + cA];
            float4 vB = *(const float4*)&Vs[j * 132 + cB];
#pragma unroll
            for (int i = 0; i < 4; i++) {
                float p = KP[(tr + 16 * i) * 68 + j];
                O[i][0] += p * vA.x; O[i][1] += p * vA.y;
                O[i][2] += p * vA.z; O[i][3] += p * vA.w;
                O[i][4] += p * vB.x; O[i][5] += p * vB.y;
                O[i][6] += p * vB.z; O[i][7] += p * vB.w;
            }
        }
        __syncthreads();
    }

#pragma unroll
    for (int i = 0; i < 4; i++) {
        int rl = tr + 16 * i;
        float inv = 1.f / Lrow[rl];
        float4 oA = make_float4(O[i][0] * inv, O[i][1] * inv, O[i][2] * inv, O[i][3] * inv);
        float4 oB = make_float4(O[i][4] * inv, O[i][5] * inv, O[i][6] * inv, O[i][7] * inv);
        size_t base = (size_t)(tok0 + rl) * (NH * HD) + hq * HD;
        *(float4*)&o[base + cA] = oA;
        *(float4*)&o[base + cB] = oB;
    }
}

// ---------------- SiLU(gate) * up, in place on gate ----------------
__global__ void silu_mul_kernel(float* __restrict__ gbuf, const float* __restrict__ ubuf, int n4) {
    int i = blockIdx.x * blockDim.x + threadIdx.x;
    if (i < n4) {
        float4 gv = ((const float4*)gbuf)[i];
        float4 uv = ((const float4*)ubuf)[i];
        gv.x = gv.x / (1.f + __expf(-gv.x)) * uv.x;
        gv.y = gv.y / (1.f + __expf(-gv.y)) * uv.y;
        gv.z = gv.z / (1.f + __expf(-gv.z)) * uv.z;
        gv.w = gv.w / (1.f + __expf(-gv.w)) * uv.w;
        ((float4*)gbuf)[i] = gv;
    }
}

// ---------------- host orchestration ----------------
extern "C" void kernel_launch(void* const* d_in, const int* in_sizes, int n_in,
                              void* d_out, int out_size) {
    const float* x    = (const float*)d_in[0];
    const float* cosb = (const float*)d_in[2];
    const float* sinb = (const float*)d_in[3];
    const float* wq   = (const float*)d_in[4];
    const float* bq   = (const float*)d_in[5];
    const float* wk   = (const float*)d_in[6];
    const float* bk   = (const float*)d_in[7];
    const float* wv   = (const float*)d_in[8];
    const float* bv   = (const float*)d_in[9];
    const float* wo   = (const float*)d_in[10];
    const float* qnw  = (const float*)d_in[11];
    const float* knw  = (const float*)d_in[12];
    const float* ln1  = (const float*)d_in[13];
    const float* ln2  = (const float*)d_in[14];
    const float* wg   = (const float*)d_in[15];
    const float* wu   = (const float*)d_in[16];
    const float* wd   = (const float*)d_in[17];
    float* out = (float*)d_out;

    float *h_, *q_, *k_, *v_, *attn_, *x1_, *gate_, *up_;
    cudaGetSymbolAddress((void**)&h_,    g_h);
    cudaGetSymbolAddress((void**)&q_,    g_q);
    cudaGetSymbolAddress((void**)&k_,    g_k);
    cudaGetSymbolAddress((void**)&v_,    g_v);
    cudaGetSymbolAddress((void**)&attn_, g_attn);
    cudaGetSymbolAddress((void**)&x1_,   g_x1);
    cudaGetSymbolAddress((void**)&gate_, g_gate);
    cudaGetSymbolAddress((void**)&up_,   g_up);

    const int attn_smem = ATTN_SMEM_FLOATS * 4;
    cudaFuncSetAttribute(attn_kernel, cudaFuncAttributeMaxDynamicSharedMemorySize, attn_smem);
    cudaFuncSetAttribute(gemm_tf32, cudaFuncAttributeMaxDynamicSharedMemorySize, GEMM_SMEM_BYTES);

    // 1. h = RMSNorm(x, ln1)
    rmsnorm_kernel<<<TTOK, 256>>>(x, ln1, h_);
    // 2-4. q/k/v projections
    gemm_tf32<<<dim3(HIDN / 128, TTOK / 128), 256, GEMM_SMEM_BYTES>>>(h_, wq, bq, nullptr, q_, TTOK, HIDN, HIDN);
    gemm_tf32<<<dim3((NKV * HD) / 128, TTOK / 128), 256, GEMM_SMEM_BYTES>>>(h_, wk, bk, nullptr, k_, TTOK, NKV * HD, HIDN);
    gemm_tf32<<<dim3((NKV * HD) / 128, TTOK / 128), 256, GEMM_SMEM_BYTES>>>(h_, wv, bv, nullptr, v_, TTOK, NKV * HD, HIDN);
    // 5. per-head RMSNorm + RoPE
    qknorm_rope_kernel<<<dim3(TTOK, NH + NKV), 128>>>(q_, k_, qnw, knw, cosb, sinb);
    // 6. causal flash attention
    attn_kernel<<<dim3(SEQ / 64, NH, BATCH), 256, attn_smem>>>(q_, k_, v_, attn_);
    // 7. x1 = x + attn @ wo^T
    gemm_tf32<<<dim3(HIDN / 128, TTOK / 128), 256, GEMM_SMEM_BYTES>>>(attn_, wo, nullptr, x, x1_, TTOK, HIDN, HIDN);
    // 8. h2 = RMSNorm(x1, ln2)
    rmsnorm_kernel<<<TTOK, 256>>>(x1_, ln2, h_);
    // 9-10. gate / up projections
    gemm_tf32<<<dim3(INTERN / 128, TTOK / 128), 256, GEMM_SMEM_BYTES>>>(h_, wg, nullptr, nullptr, gate_, TTOK, INTERN, HIDN);
    gemm_tf32<<<dim3(INTERN / 128, TTOK / 128), 256, GEMM_SMEM_BYTES>>>(h_, wu, nullptr, nullptr, up_, TTOK, INTERN, HIDN);
    // 11. gate = silu(gate) * up
    {
        int n4 = TTOK * INTERN / 4;
        silu_mul_kernel<<<(n4 + 255) / 256, 256>>>(gate_, up_, n4);
    }
    // 12. out = x1 + gate @ wd^T
    gemm_tf32<<<dim3(HIDN / 128, TTOK / 128), 256, GEMM_SMEM_BYTES>>>(gate_, wd, nullptr, x1_, out, TTOK, HIDN, INTERN);
}